// round 16
// baseline (speedup 1.0000x reference)
#include <cuda_runtime.h>

typedef unsigned long long ull;

#define BATCH 256
#define NTOK  256
#define NFULL 257
#define DIM   768
#define KC    8
#define VCNT  10000
#define ITERS 4
#define NTHREADS 512

#define CHTOK 16                 /* tokens per chunk */
#define NCHK  16                 /* chunks per iteration (256/16) */
#define TOTCH (ITERS * NCHK)     /* 64 A-chunks total */
#define TKS   386                /* ull stride per token row (conflict-free banking) */
#define DFS   386                /* ull stride per diff row */
#define BUFULL (CHTOK * TKS)     /* 6176 ull per buffer slot */

/* dynamic smem layout (bytes) — total 225856 < 232448 cap */
#define OFF_TK   0
#define SZ_TK    (4 * BUFULL * 8)          /* 197632 : 4-slot token ring */
#define OFF_DFT  (OFF_TK + SZ_TK)          /* 197632 */
#define SZ_DFT   (KC * DFS * 8)            /* 24704  : diff[k][dp] */
#define OFF_A1   (OFF_DFT + SZ_DFT)        /* 222336 */
#define SZ_A1    (2 * CHTOK * KC * 4)      /* 1024   : double-buffered f32 assignments */
#define OFF_RED  (OFF_A1 + SZ_A1)          /* 223360 */
#define SZ_RED   (4 * 128 * 4)             /* 2048   : A-team partial slices */
#define OFF_PART (OFF_RED + SZ_RED)        /* 225408 */
#define SZ_PART  (6 * 16 * 4)              /* 384    : B-team norm partials */
#define OFF_INV  (OFF_PART + SZ_PART)      /* 225792 */
#define KM_SMEM  (OFF_INV + 64)            /* 225856 */

#define FXSCALE     1099511627776.0        /* 2^40 */
#define INV_FXSCALE (1.0 / 1099511627776.0)

__device__ ull g_acc[VCNT];   // fixed-point scatter bins (integer adds: deterministic)

// ---------------- packed f32x2 helpers (sm_103a) ----------------
__device__ __forceinline__ ull ffma2(ull a, ull b, ull c) {
    ull d; asm("fma.rn.f32x2 %0, %1, %2, %3;" : "=l"(d) : "l"(a), "l"(b), "l"(c)); return d;
}
__device__ __forceinline__ ull fadd2(ull a, ull b) {
    ull d; asm("add.rn.f32x2 %0, %1, %2;" : "=l"(d) : "l"(a), "l"(b)); return d;
}
__device__ __forceinline__ ull pack2(float x, float y) {
    ull r; asm("mov.b64 %0, {%1, %2};" : "=l"(r) : "f"(x), "f"(y)); return r;
}
__device__ __forceinline__ void unpack2(ull v, float& x, float& y) {
    asm("mov.b64 {%0, %1}, %2;" : "=f"(x), "=f"(y) : "l"(v));
}

// coalesced cp.async stage of one 16-token chunk (16 x 768 floats), 512 threads
__device__ __forceinline__ void stage_chunk(ull* dstbuf, const float* src, int tid) {
    #pragma unroll
    for (int i = 0; i < 6; ++i) {
        int f = tid + NTHREADS * i;       // 0..3071 16B-segments
        int r = f / 192;                  // token row 0..15
        int s = f - r * 192;              // segment within row
        unsigned d = (unsigned)__cvta_generic_to_shared(dstbuf + r * TKS + s * 2);
        asm volatile("cp.async.cg.shared.global [%0], [%1], 16;"
                     :: "r"(d), "l"(src + (size_t)r * DIM + s * 4));
    }
}

// =====================================================================
// Kernel 1: warp-specialized pipelined k-means.
//   A team = warps 0-7  : assignments for chunk ca   (named bar 1, 256)
//   B team = warps 8-13 : centroid accum for chunk ca-1; norms/diff at
//                         flush (named bar 2, 192)
//   all 512 threads     : cp.async staging into a 4-slot ring
// One global __syncthreads per pipeline step.
// =====================================================================
__global__ void __launch_bounds__(NTHREADS, 1)
kmeans_kernel(const float* __restrict__ tokens,
              const float* __restrict__ vc,
              const int*   __restrict__ topk,
              float*       __restrict__ out_assign)
{
    extern __shared__ __align__(16) char smem[];
    ull*   s_tk  = (ull*)(smem + OFF_TK);
    ull*   s_dfT = (ull*)(smem + OFF_DFT);
    float* s_a1  = (float*)(smem + OFF_A1);
    float* s_red = (float*)(smem + OFF_RED);
    float (*s_part)[16] = (float(*)[16])(smem + OFF_PART);
    float* s_inv = (float*)(smem + OFF_INV);

    const int b    = blockIdx.x;
    const int tid  = threadIdx.x;
    const int lane = tid & 31;
    const int w    = tid >> 5;

    const float* tokbase = tokens + ((size_t)b * NFULL + 1) * DIM;

    // ---- prologue: stage chunks 0,1 into slots 0,1 (2 committed groups)
    stage_chunk(s_tk,              tokbase,                       tid);
    asm volatile("cp.async.commit_group;");
    stage_chunk(s_tk + BUFULL,     tokbase + (size_t)CHTOK * DIM, tid);
    asm volatile("cp.async.commit_group;");

    // ---- initial diff = c1hat - c0hat, built by A team (warp w -> k=w)
    if (w < 8) {
        const int k   = w;
        const int idx = topk[b * KC + k];
        const float4* r0 = (const float4*)(vc + (size_t)idx * 2 * DIM);
        const float4* r1 = r0 + DIM / 4;
        float ss0 = 0.f, ss1 = 0.f;
        for (int j = lane; j < DIM / 4; j += 32) {
            float4 a = r0[j]; ss0 += a.x*a.x + a.y*a.y + a.z*a.z + a.w*a.w;
            float4 c = r1[j]; ss1 += c.x*c.x + c.y*c.y + c.z*c.z + c.w*c.w;
        }
        #pragma unroll
        for (int off = 16; off; off >>= 1) {
            ss0 += __shfl_down_sync(0xffffffffu, ss0, off);
            ss1 += __shfl_down_sync(0xffffffffu, ss1, off);
        }
        ss0 = __shfl_sync(0xffffffffu, ss0, 0);
        ss1 = __shfl_sync(0xffffffffu, ss1, 0);
        const float i0 = 1.f / fmaxf(sqrtf(ss0), 1e-12f);
        const float i1 = 1.f / fmaxf(sqrtf(ss1), 1e-12f);
        const float2* p0 = (const float2*)(vc + (size_t)idx * 2 * DIM);
        const float2* p1 = p0 + DIM / 2;
        for (int dp = lane; dp < DIM / 2; dp += 32) {
            float2 a = p0[dp];
            float2 c = p1[dp];
            s_dfT[k * DFS + dp] = pack2(c.x * i1 - a.x * i0, c.y * i1 - a.y * i0);
        }
    }

    // ---- B-team persistent state
    const int bt = tid - 256;                 // 0..191 for B team
    ull aE[KC], aO[KC];                       // c1 accumulators: dims (4bt,4bt+1),(4bt+2,4bt+3)
    ull tsA = 0ull, tsB = 0ull;               // tokensum (iter-0 fold)
    float tsx0 = 0.f, tsx1 = 0.f, tsx2 = 0.f, tsx3 = 0.f;

    int ca = 0;                               // global A-chunk counter (uniform)

    for (int it = 0; it < ITERS; ++it) {
        if (tid >= 256 && tid < 448) {
            #pragma unroll
            for (int k = 0; k < KC; ++k) { aE[k] = 0ull; aO[k] = 0ull; }
        }

        for (int s = 0; s <= NCHK; ++s) {
            const bool Aact = (s < NCHK);

            // wait: all-but-newest groups complete -> A's chunk (committed
            // >=2 groups ago) is ready. Final chunk needs wait 0.
            if (Aact && ca == TOTCH - 1) asm volatile("cp.async.wait_group 0;");
            else                         asm volatile("cp.async.wait_group 1;");
            __syncthreads();   // orders prior-step reads before new staging

            if (Aact && (ca + 2 < TOTCH)) {
                const int nc = ca + 2;
                stage_chunk(s_tk + (size_t)(nc & 3) * BUFULL,
                            tokbase + (size_t)(nc & 15) * CHTOK * DIM, tid);
                asm volatile("cp.async.commit_group;");
            }

            // ================= A team: assignments for chunk ca =================
            if (Aact && tid < 256) {
                const ull* buf = s_tk + (size_t)(ca & 3) * BUFULL;
                const int tg = lane >> 2;       // 0..7
                const int kg = lane & 3;
                const ulonglong2* tb = (const ulonglong2*)buf;
                const ulonglong2* db = (const ulonglong2*)s_dfT;
                const int j0 = w * 24;
                ull ac00=0, ac01=0, ac10=0, ac11=0;
                #pragma unroll 4
                for (int j = 0; j < 24; ++j) {
                    const int jj = j0 + j;
                    ulonglong2 d0 = db[(2*kg    ) * 193 + jj];
                    ulonglong2 d1 = db[(2*kg + 1) * 193 + jj];
                    ulonglong2 t0 = tb[(tg     ) * 193 + jj];
                    ulonglong2 t1 = tb[(tg + 8 ) * 193 + jj];
                    ac00 = ffma2(t0.x, d0.x, ac00); ac00 = ffma2(t0.y, d0.y, ac00);
                    ac01 = ffma2(t0.x, d1.x, ac01); ac01 = ffma2(t0.y, d1.y, ac01);
                    ac10 = ffma2(t1.x, d0.x, ac10); ac10 = ffma2(t1.y, d0.y, ac10);
                    ac11 = ffma2(t1.x, d1.x, ac11); ac11 = ffma2(t1.y, d1.y, ac11);
                }
                float p00, p01, p10, p11;
                { float x, y;
                  unpack2(ac00, x, y); p00 = x + y;
                  unpack2(ac01, x, y); p01 = x + y;
                  unpack2(ac10, x, y); p10 = x + y;
                  unpack2(ac11, x, y); p11 = x + y; }
                // 2-round fixed-order cross-warp reduction into 4 slices
                const int slice = w & 3;
                float2* red = (float2*)(s_red + slice * 128);
                const int pos = tg * 4 + kg;    // == lane
                if (w >= 4) {
                    red[pos]      = make_float2(p00, p01);
                    red[pos + 32] = make_float2(p10, p11);
                }
                asm volatile("bar.sync 1, 256;" ::: "memory");
                if (w < 4) {
                    float2 v0 = red[pos];
                    red[pos]      = make_float2(v0.x + p00, v0.y + p01);
                    float2 v1 = red[pos + 32];
                    red[pos + 32] = make_float2(v1.x + p10, v1.y + p11);
                }
                asm volatile("bar.sync 1, 256;" ::: "memory");
                if (tid < 128) {   // tid = tok*8 + k
                    float dot = ((s_red[tid] + s_red[128 + tid])
                                 + s_red[256 + tid]) + s_red[384 + tid];
                    const float af = dot > 0.f ? 1.f : 0.f;
                    s_a1[(ca & 1) * 128 + tid] = af;
                    if (it == ITERS - 1)
                        out_assign[((size_t)b * NTOK + (ca & 15) * CHTOK + (tid >> 3)) * KC
                                   + (tid & 7)] = af;
                }
            }

            // ================= B team: accumulate chunk ca-1 =================
            if (s >= 1 && tid >= 256 && tid < 448) {
                const int cb = ca - 1;
                const ull* bb = s_tk + (size_t)(cb & 3) * BUFULL + 2 * bt;
                const float* a1p = s_a1 + (cb & 1) * 128;
                #pragma unroll 4
                for (int n = 0; n < CHTOK; ++n) {
                    ulonglong2 t = *(const ulonglong2*)(bb + n * TKS);
                    float4 qa = *(const float4*)(a1p + n * 8);
                    float4 qb = *(const float4*)(a1p + n * 8 + 4);
                    ull m0 = pack2(qa.x, qa.x), m1 = pack2(qa.y, qa.y);
                    ull m2 = pack2(qa.z, qa.z), m3 = pack2(qa.w, qa.w);
                    ull m4 = pack2(qb.x, qb.x), m5 = pack2(qb.y, qb.y);
                    ull m6 = pack2(qb.z, qb.z), m7 = pack2(qb.w, qb.w);
                    aE[0] = ffma2(t.x, m0, aE[0]);  aO[0] = ffma2(t.y, m0, aO[0]);
                    aE[1] = ffma2(t.x, m1, aE[1]);  aO[1] = ffma2(t.y, m1, aO[1]);
                    aE[2] = ffma2(t.x, m2, aE[2]);  aO[2] = ffma2(t.y, m2, aO[2]);
                    aE[3] = ffma2(t.x, m3, aE[3]);  aO[3] = ffma2(t.y, m3, aO[3]);
                    aE[4] = ffma2(t.x, m4, aE[4]);  aO[4] = ffma2(t.y, m4, aO[4]);
                    aE[5] = ffma2(t.x, m5, aE[5]);  aO[5] = ffma2(t.y, m5, aO[5]);
                    aE[6] = ffma2(t.x, m6, aE[6]);  aO[6] = ffma2(t.y, m6, aO[6]);
                    aE[7] = ffma2(t.x, m7, aE[7]);  aO[7] = ffma2(t.y, m7, aO[7]);
                    if (it == 0) { tsA = fadd2(tsA, t.x); tsB = fadd2(tsB, t.y); }
                }

                // ---- iteration flush: norms + next diff (B team only) ----
                if (s == NCHK) {
                    if (it == 0) { unpack2(tsA, tsx0, tsx1); unpack2(tsB, tsx2, tsx3); }

                    float ssl[16];
                    #pragma unroll
                    for (int k = 0; k < KC; ++k) {
                        float x0, x1, x2, x3;
                        unpack2(aE[k], x0, x1); unpack2(aO[k], x2, x3);
                        ssl[k] = x0*x0 + x1*x1 + x2*x2 + x3*x3;
                        float y0 = tsx0 - x0, y1 = tsx1 - x1,
                              y2 = tsx2 - x2, y3 = tsx3 - x3;
                        ssl[8 + k] = y0*y0 + y1*y1 + y2*y2 + y3*y3;
                    }
                    #pragma unroll
                    for (int i = 0; i < 16; ++i) {
                        float v = ssl[i];
                        #pragma unroll
                        for (int off = 16; off; off >>= 1)
                            v += __shfl_down_sync(0xffffffffu, v, off);
                        if (lane == 0) s_part[w - 8][i] = v;
                    }
                    asm volatile("bar.sync 2, 192;" ::: "memory");
                    if (bt < 16) {
                        float v = ((s_part[0][bt] + s_part[1][bt]) + (s_part[2][bt] + s_part[3][bt]))
                                  + (s_part[4][bt] + s_part[5][bt]);
                        // fixed left-fold order, deterministic
                        float vv = s_part[0][bt];
                        vv += s_part[1][bt]; vv += s_part[2][bt];
                        vv += s_part[3][bt]; vv += s_part[4][bt]; vv += s_part[5][bt];
                        (void)v;
                        s_inv[bt] = 1.f / fmaxf(sqrtf(vv), 1e-12f);
                    }
                    asm volatile("bar.sync 2, 192;" ::: "memory");
                    const int dp0 = bt * 2;
                    #pragma unroll
                    for (int k = 0; k < KC; ++k) {
                        const float i1 = s_inv[k], i0 = s_inv[8 + k];
                        float x0, x1, x2, x3;
                        unpack2(aE[k], x0, x1); unpack2(aO[k], x2, x3);
                        const float y0 = tsx0 - x0, y1 = tsx1 - x1,
                                    y2 = tsx2 - x2, y3 = tsx3 - x3;
                        s_dfT[k * DFS + dp0]     = pack2(x0*i1 - y0*i0, x1*i1 - y1*i0);
                        s_dfT[k * DFS + dp0 + 1] = pack2(x2*i1 - y2*i0, x3*i1 - y3*i0);
                    }
                    if (it == ITERS - 1 && bt == 0) {
                        #pragma unroll
                        for (int k = 0; k < KC; ++k) {
                            float x0, x1;
                            unpack2(aE[k], x0, x1);
                            double v = (double)((tsx0 - x0) * s_inv[8 + k]);
                            long long q = llrint(v * FXSCALE);
                            atomicAdd(&g_acc[topk[b * KC + k]], (ull)q);
                        }
                    }
                }
            }

            if (Aact) ca++;
        }
    }
}

// =====================================================================
// Kernel 2: vc_new = l2norm(vc with delta at [v,0,0]) — warp-per-row.
// 6 float4/lane, xor-butterfly reduce, no block barriers. c=0 warp
// consumes + resets g_acc[v] (replay-invariant).
// =====================================================================
__global__ __launch_bounds__(256)
void vcnew_kernel(const float* __restrict__ vc, float* __restrict__ out)
{
    const int gw   = (blockIdx.x * 256 + threadIdx.x) >> 5;   // global warp = row id
    const int lane = threadIdx.x & 31;
    if (gw >= VCNT * 2) return;
    const int v = gw >> 1;
    const int c = gw & 1;

    const float4* src = (const float4*)(vc + (size_t)gw * DIM);
    float4 x[6];
    #pragma unroll
    for (int i = 0; i < 6; ++i) x[i] = src[lane + 32 * i];   // MLP 6, coalesced

    if (c == 0 && lane == 0) {
        x[0].x += (float)((double)(long long)g_acc[v] * INV_FXSCALE);
        g_acc[v] = 0ull;                                     // reset for next replay
    }

    float ss = 0.f;
    #pragma unroll
    for (int i = 0; i < 6; ++i)
        ss += (x[i].x*x[i].x + x[i].y*x[i].y) + (x[i].z*x[i].z + x[i].w*x[i].w);
    #pragma unroll
    for (int off = 16; off; off >>= 1)
        ss += __shfl_xor_sync(0xffffffffu, ss, off);         // butterfly: all lanes

    const float sc = 1.f / fmaxf(sqrtf(ss), 1e-12f);
    float4* dst = (float4*)(out + (size_t)gw * DIM);
    #pragma unroll
    for (int i = 0; i < 6; ++i)
        dst[lane + 32 * i] = make_float4(x[i].x * sc, x[i].y * sc,
                                         x[i].z * sc, x[i].w * sc);
}

// =====================================================================
extern "C" void kernel_launch(void* const* d_in, const int* in_sizes, int n_in,
                              void* d_out, int out_size)
{
    const float* tokens = nullptr;
    const float* vc     = nullptr;
    const int*   topk   = nullptr;
    for (int i = 0; i < n_in; ++i) {
        if (in_sizes[i] == BATCH * NFULL * DIM)      tokens = (const float*)d_in[i];
        else if (in_sizes[i] == VCNT * 2 * DIM)      vc     = (const float*)d_in[i];
        else if (in_sizes[i] == BATCH * KC)          topk   = (const int*)d_in[i];
    }
    float* out = (float*)d_out;   // [assignments (256,256,8) | vc_new (10000,2,768)]

    static bool attr_set = false;
    if (!attr_set) {
        cudaFuncSetAttribute(kmeans_kernel,
                             cudaFuncAttributeMaxDynamicSharedMemorySize, KM_SMEM);
        attr_set = true;
    }

    kmeans_kernel<<<BATCH, NTHREADS, KM_SMEM>>>(tokens, vc, topk, out);
    vcnew_kernel<<<(VCNT * 2 * 32 + 255) / 256, 256>>>(vc, out + (size_t)BATCH * NTOK * KC);
}